// round 1
// baseline (speedup 1.0000x reference)
#include <cuda_runtime.h>
#include <math.h>

// ---------------- problem constants ----------------
#define M_TOK 32768          // 8 * 4096 tokens
#define SEQ   4096
#define DIM   384
#define NH    6
#define HD    64
#define BH    48             // batch*heads
#define QKVN  1152
#define HID   1536

// ---------------- scratch (static device arrays; no allocation) ----------------
__device__ float g_ln  [(size_t)M_TOK * DIM];
__device__ float g_qkv [(size_t)M_TOK * QKVN];
__device__ float g_attn[(size_t)M_TOK * DIM];
__device__ float g_x1  [(size_t)M_TOK * DIM];
__device__ float g_mlp [(size_t)M_TOK * HID];
__device__ float g_kv  [BH * HD * HD];
__device__ float g_ksum[BH * HD];

// ---------------- LayerNorm: one block per row of 384 ----------------
__global__ __launch_bounds__(128) void ln_kernel(
    const float* __restrict__ x, const float* __restrict__ gma,
    const float* __restrict__ bta, float* __restrict__ out)
{
    const int row = blockIdx.x;
    const float* xr = x + (size_t)row * DIM;
    float* orow = out + (size_t)row * DIM;
    const int tid = threadIdx.x;

    float v0 = xr[tid], v1 = xr[tid + 128], v2 = xr[tid + 256];
    float s  = v0 + v1 + v2;
    float sq = v0*v0 + v1*v1 + v2*v2;
    #pragma unroll
    for (int o = 16; o > 0; o >>= 1) {
        s  += __shfl_down_sync(0xffffffffu, s,  o);
        sq += __shfl_down_sync(0xffffffffu, sq, o);
    }
    __shared__ float ss[4], sqs[4];
    const int w = tid >> 5;
    if ((tid & 31) == 0) { ss[w] = s; sqs[w] = sq; }
    __syncthreads();
    if (tid == 0) {
        float S  = ss[0] + ss[1] + ss[2] + ss[3];
        float SQ = sqs[0] + sqs[1] + sqs[2] + sqs[3];
        float mean = S * (1.f / DIM);
        float var  = SQ * (1.f / DIM) - mean * mean;
        ss[0]  = mean;
        sqs[0] = rsqrtf(var + 1e-5f);
    }
    __syncthreads();
    const float mean = ss[0], inv = sqs[0];
    orow[tid      ] = (v0 - mean) * inv * gma[tid      ] + bta[tid      ];
    orow[tid + 128] = (v1 - mean) * inv * gma[tid + 128] + bta[tid + 128];
    orow[tid + 256] = (v2 - mean) * inv * gma[tid + 256] + bta[tid + 256];
}

// ---------------- SGEMM 128x128x8, 256 threads, 8x8 per thread ----------------
// C[M,N] = A[M,K] @ W[K,N] + bias, fused epilogue per MODE:
//   MODE 0: qkv  -> phi(x)=elu(x)+1 on columns < 768 (q and k parts)
//   MODE 1: proj -> += residual
//   MODE 2: fc1  -> tanh-approx gelu
//   MODE 3: fc2  -> += residual
template<int MODE>
__global__ __launch_bounds__(256) void gemm_kernel(
    const float* __restrict__ A, const float* __restrict__ W,
    const float* __restrict__ bias, const float* __restrict__ res,
    float* __restrict__ C, int N, int K)
{
    __shared__ float As[8][128];
    __shared__ float Bs[8][128];
    const int tid = threadIdx.x;
    const int bm = blockIdx.y * 128;
    const int bn = blockIdx.x * 128;
    const int tx = tid & 15, ty = tid >> 4;

    const int arow = tid >> 1;
    const int acol = (tid & 1) << 2;
    const int brow = tid >> 5;
    const int bcol = (tid & 31) << 2;

    const float* Ap = A + (size_t)(bm + arow) * K + acol;
    const float* Wp = W + (size_t)brow * N + bn + bcol;

    float acc[8][8] = {};

    for (int k0 = 0; k0 < K; k0 += 8) {
        const float4 a  = *(const float4*)(Ap + k0);
        const float4 bv = *(const float4*)(Wp + (size_t)k0 * N);
        __syncthreads();
        As[acol + 0][arow] = a.x;
        As[acol + 1][arow] = a.y;
        As[acol + 2][arow] = a.z;
        As[acol + 3][arow] = a.w;
        *(float4*)&Bs[brow][bcol] = bv;
        __syncthreads();
        #pragma unroll
        for (int kk = 0; kk < 8; kk++) {
            float af[8], bf[8];
            *(float4*)&af[0] = *(const float4*)&As[kk][ty * 8];
            *(float4*)&af[4] = *(const float4*)&As[kk][ty * 8 + 4];
            *(float4*)&bf[0] = *(const float4*)&Bs[kk][tx * 8];
            *(float4*)&bf[4] = *(const float4*)&Bs[kk][tx * 8 + 4];
            #pragma unroll
            for (int i = 0; i < 8; i++)
                #pragma unroll
                for (int j = 0; j < 8; j++)
                    acc[i][j] = fmaf(af[i], bf[j], acc[i][j]);
        }
    }

    #pragma unroll
    for (int i = 0; i < 8; i++) {
        const int m  = bm + ty * 8 + i;
        const int nb = bn + tx * 8;
        float* cp = C + (size_t)m * N + nb;
        const float* rp = (MODE == 1 || MODE == 3) ? (res + (size_t)m * N + nb) : nullptr;
        #pragma unroll
        for (int g4 = 0; g4 < 2; g4++) {
            float t[4];
            #pragma unroll
            for (int j = 0; j < 4; j++) {
                const int jj = g4 * 4 + j;
                float v = acc[i][jj] + bias[nb + jj];
                if (MODE == 0) {
                    if (nb + jj < 768) v = (v > 0.f) ? (v + 1.f) : __expf(v);
                }
                if (MODE == 2) {
                    v = 0.5f * v * (1.f + tanhf(0.7978845608028654f * (v + 0.044715f * v * v * v)));
                }
                if (MODE == 1 || MODE == 3) v += rp[jj];
                t[j] = v;
            }
            *(float4*)(cp + g4 * 4) = make_float4(t[0], t[1], t[2], t[3]);
        }
    }
}

// ---------------- zero kv state ----------------
__global__ void zero_kv_kernel()
{
    const int i = blockIdx.x * blockDim.x + threadIdx.x;
    if (i < BH * HD * HD) g_kv[i] = 0.f;
    if (i < BH * HD)      g_ksum[i] = 0.f;
}

// ---------------- kv-state: kv[bh] += K^T V over a 512-row chunk ----------------
__global__ __launch_bounds__(256) void kv_kernel()
{
    const int bh = blockIdx.y;
    const int b  = bh / NH, h = bh % NH;
    const int nbase = blockIdx.x * 512;

    __shared__ float ks[64][64];
    __shared__ float vs[64][64];

    const int tid = threadIdx.x;
    const int tx = tid & 15, ty = tid >> 4;
    const int e0 = tx * 4, d0 = ty * 4;

    float acc[4][4] = {};
    float ksacc = 0.f;

    for (int rb = 0; rb < 512; rb += 64) {
        const float* base = g_qkv + (size_t)(b * SEQ + nbase + rb) * QKVN + h * HD;
        for (int i = tid; i < 1024; i += 256) {
            const int r = i >> 4, c = (i & 15) << 2;
            *(float4*)&ks[r][c] = *(const float4*)(base + (size_t)r * QKVN + 384 + c);
            *(float4*)&vs[r][c] = *(const float4*)(base + (size_t)r * QKVN + 768 + c);
        }
        __syncthreads();
        #pragma unroll 8
        for (int r = 0; r < 64; r++) {
            const float4 a  = *(const float4*)&ks[r][d0];
            const float4 bb = *(const float4*)&vs[r][e0];
            acc[0][0] += a.x * bb.x; acc[0][1] += a.x * bb.y; acc[0][2] += a.x * bb.z; acc[0][3] += a.x * bb.w;
            acc[1][0] += a.y * bb.x; acc[1][1] += a.y * bb.y; acc[1][2] += a.y * bb.z; acc[1][3] += a.y * bb.w;
            acc[2][0] += a.z * bb.x; acc[2][1] += a.z * bb.y; acc[2][2] += a.z * bb.z; acc[2][3] += a.z * bb.w;
            acc[3][0] += a.w * bb.x; acc[3][1] += a.w * bb.y; acc[3][2] += a.w * bb.z; acc[3][3] += a.w * bb.w;
        }
        if (tid < 64) {
            #pragma unroll
            for (int r = 0; r < 64; r++) ksacc += ks[r][tid];
        }
        __syncthreads();
    }

    float* kvp = g_kv + bh * (HD * HD);
    #pragma unroll
    for (int i = 0; i < 4; i++)
        #pragma unroll
        for (int j = 0; j < 4; j++)
            atomicAdd(&kvp[(d0 + i) * HD + (e0 + j)], acc[i][j]);
    if (tid < 64) atomicAdd(&g_ksum[bh * HD + tid], ksacc);
}

// ---------------- attn: o[n,e] = z[n] * sum_d q[n,d] * kv[d,e] ----------------
__global__ __launch_bounds__(256) void attn_kernel()
{
    const int bh = blockIdx.y;
    const int b  = bh / NH, h = bh % NH;
    const int nbase = blockIdx.x * 64;

    __shared__ float qs[64][64];
    __shared__ float kvs[64][64];
    __shared__ float kss[64];
    __shared__ float zs[64];

    const int tid = threadIdx.x;

    for (int i = tid; i < 1024; i += 256) {
        const int r = i >> 4, c = (i & 15) << 2;
        *(float4*)&kvs[r][c] = *(const float4*)(g_kv + bh * (HD * HD) + r * HD + c);
    }
    if (tid < 64) kss[tid] = g_ksum[bh * HD + tid];

    const float* qbase = g_qkv + (size_t)(b * SEQ + nbase) * QKVN + h * HD;
    for (int i = tid; i < 1024; i += 256) {
        const int r = i >> 4, c = (i & 15) << 2;
        *(float4*)&qs[r][c] = *(const float4*)(qbase + (size_t)r * QKVN + c);
    }
    __syncthreads();

    if (tid < 64) {
        float dot = 0.f;
        #pragma unroll
        for (int d = 0; d < 64; d++) dot += qs[tid][d] * kss[d];
        zs[tid] = 1.f / (dot + 1e-6f);
    }
    __syncthreads();

    const int tx = tid & 15, ty = tid >> 4;
    const int e0 = tx * 4, r0 = ty * 4;
    float acc[4][4] = {};
    #pragma unroll 8
    for (int d = 0; d < 64; d++) {
        const float4 bb = *(const float4*)&kvs[d][e0];
        const float a0 = qs[r0 + 0][d];
        const float a1 = qs[r0 + 1][d];
        const float a2 = qs[r0 + 2][d];
        const float a3 = qs[r0 + 3][d];
        acc[0][0] += a0 * bb.x; acc[0][1] += a0 * bb.y; acc[0][2] += a0 * bb.z; acc[0][3] += a0 * bb.w;
        acc[1][0] += a1 * bb.x; acc[1][1] += a1 * bb.y; acc[1][2] += a1 * bb.z; acc[1][3] += a1 * bb.w;
        acc[2][0] += a2 * bb.x; acc[2][1] += a2 * bb.y; acc[2][2] += a2 * bb.z; acc[2][3] += a2 * bb.w;
        acc[3][0] += a3 * bb.x; acc[3][1] += a3 * bb.y; acc[3][2] += a3 * bb.z; acc[3][3] += a3 * bb.w;
    }

    #pragma unroll
    for (int i = 0; i < 4; i++) {
        const float z = zs[r0 + i];
        float* op = g_attn + (size_t)(b * SEQ + nbase + r0 + i) * DIM + h * HD + e0;
        *(float4*)op = make_float4(acc[i][0] * z, acc[i][1] * z, acc[i][2] * z, acc[i][3] * z);
    }
}

// ---------------- launch ----------------
extern "C" void kernel_launch(void* const* d_in, const int* in_sizes, int n_in,
                              void* d_out, int out_size)
{
    const float* x      = (const float*)d_in[0];
    const float* n1g    = (const float*)d_in[1];
    const float* n1b    = (const float*)d_in[2];
    const float* qkv_w  = (const float*)d_in[3];
    const float* qkv_b  = (const float*)d_in[4];
    const float* proj_w = (const float*)d_in[5];
    const float* proj_b = (const float*)d_in[6];
    const float* n2g    = (const float*)d_in[7];
    const float* n2b    = (const float*)d_in[8];
    const float* fc1_w  = (const float*)d_in[9];
    const float* fc1_b  = (const float*)d_in[10];
    const float* fc2_w  = (const float*)d_in[11];
    const float* fc2_b  = (const float*)d_in[12];
    float* out = (float*)d_out;

    void *p_ln, *p_qkv, *p_attn, *p_x1, *p_mlp;
    cudaGetSymbolAddress(&p_ln,   g_ln);
    cudaGetSymbolAddress(&p_qkv,  g_qkv);
    cudaGetSymbolAddress(&p_attn, g_attn);
    cudaGetSymbolAddress(&p_x1,   g_x1);
    cudaGetSymbolAddress(&p_mlp,  g_mlp);
    float* ln   = (float*)p_ln;
    float* qkv  = (float*)p_qkv;
    float* attn = (float*)p_attn;
    float* x1   = (float*)p_x1;
    float* mlp  = (float*)p_mlp;

    // 1. LN1
    ln_kernel<<<M_TOK, 128>>>(x, n1g, n1b, ln);
    // 2. qkv GEMM + bias + phi on q,k
    gemm_kernel<0><<<dim3(QKVN / 128, M_TOK / 128), 256>>>(ln, qkv_w, qkv_b, nullptr, qkv, QKVN, DIM);
    // 3. zero kv state, then accumulate kv = K^T V and ksum per (b,h)
    zero_kv_kernel<<<(BH * HD * HD + 255) / 256, 256>>>();
    kv_kernel<<<dim3(SEQ / 512, BH), 256>>>();
    // 4. attn = (q @ kv) * z
    attn_kernel<<<dim3(SEQ / 64, BH), 256>>>();
    // 5. proj GEMM + bias + residual(x) -> x1
    gemm_kernel<1><<<dim3(DIM / 128, M_TOK / 128), 256>>>(attn, proj_w, proj_b, x, x1, DIM, DIM);
    // 6. LN2
    ln_kernel<<<M_TOK, 128>>>(x1, n2g, n2b, ln);
    // 7. fc1 GEMM + bias + gelu
    gemm_kernel<2><<<dim3(HID / 128, M_TOK / 128), 256>>>(ln, fc1_w, fc1_b, nullptr, mlp, HID, DIM);
    // 8. fc2 GEMM + bias + residual(x1) -> out
    gemm_kernel<3><<<dim3(DIM / 128, M_TOK / 128), 256>>>(mlp, fc2_w, fc2_b, x1, out, DIM, HID);
}

// round 2
// speedup vs baseline: 1.7263x; 1.7263x over previous
#include <cuda_runtime.h>
#include <math.h>
#include <stdint.h>

// ---------------- problem constants ----------------
#define M_TOK 32768          // 8 * 4096 tokens
#define SEQ   4096
#define DIM   384
#define NH    6
#define HD    64
#define BH    48             // batch*heads
#define QKVN  1152
#define HID   1536

// ---------------- scratch (static device arrays; no allocation) ----------------
__device__ float g_ln  [(size_t)M_TOK * DIM];
__device__ float g_qkv [(size_t)M_TOK * QKVN];
__device__ float g_attn[(size_t)M_TOK * DIM];
__device__ float g_x1  [(size_t)M_TOK * DIM];
__device__ float g_mlp [(size_t)M_TOK * HID];
__device__ float g_kv  [BH * HD * HD];
__device__ float g_ksum[BH * HD];

// ---------------- LayerNorm: one block per row of 384 ----------------
__global__ __launch_bounds__(128) void ln_kernel(
    const float* __restrict__ x, const float* __restrict__ gma,
    const float* __restrict__ bta, float* __restrict__ out)
{
    const int row = blockIdx.x;
    const float* xr = x + (size_t)row * DIM;
    float* orow = out + (size_t)row * DIM;
    const int tid = threadIdx.x;

    float v0 = xr[tid], v1 = xr[tid + 128], v2 = xr[tid + 256];
    float s  = v0 + v1 + v2;
    float sq = v0*v0 + v1*v1 + v2*v2;
    #pragma unroll
    for (int o = 16; o > 0; o >>= 1) {
        s  += __shfl_down_sync(0xffffffffu, s,  o);
        sq += __shfl_down_sync(0xffffffffu, sq, o);
    }
    __shared__ float ss[4], sqs[4];
    const int w = tid >> 5;
    if ((tid & 31) == 0) { ss[w] = s; sqs[w] = sq; }
    __syncthreads();
    if (tid == 0) {
        float S  = ss[0] + ss[1] + ss[2] + ss[3];
        float SQ = sqs[0] + sqs[1] + sqs[2] + sqs[3];
        float mean = S * (1.f / DIM);
        float var  = SQ * (1.f / DIM) - mean * mean;
        ss[0]  = mean;
        sqs[0] = rsqrtf(var + 1e-5f);
    }
    __syncthreads();
    const float mean = ss[0], inv = sqs[0];
    orow[tid      ] = (v0 - mean) * inv * gma[tid      ] + bta[tid      ];
    orow[tid + 128] = (v1 - mean) * inv * gma[tid + 128] + bta[tid + 128];
    orow[tid + 256] = (v2 - mean) * inv * gma[tid + 256] + bta[tid + 256];
}

// ---------------- tf32 tensor-core GEMM ----------------
// C[M,N] = A[M,K] @ W[K,N] + bias, fused epilogue per MODE:
//   MODE 0: qkv  -> phi(x)=elu(x)+1 on columns < 768
//   MODE 1: proj -> += residual
//   MODE 2: fc1  -> tanh gelu
//   MODE 3: fc2  -> += residual
// Tile: 128x128x32. 256 threads = 8 warps in 2x4; warp tile 64x32 = 4x4 m16n8k8.
// Smem: As[2][128][36] (m-major, pad 4), Bs[2][32][136] (k-major, pad 8).

#define BM 128
#define BN 128
#define BK 32
#define AS_STRIDE 36
#define BS_STRIDE 136
#define AS_BUF (BM * AS_STRIDE)
#define BS_BUF (BK * BS_STRIDE)
#define GEMM_SMEM_BYTES ((2 * AS_BUF + 2 * BS_BUF) * 4)

__device__ __forceinline__ uint32_t f2tf32(float x) {
    uint32_t u;
    asm("cvt.rna.tf32.f32 %0, %1;" : "=r"(u) : "f"(x));
    return u;
}

__device__ __forceinline__ void mma_tf32(float* d, const uint32_t* a, const uint32_t* b) {
    asm volatile(
        "mma.sync.aligned.m16n8k8.row.col.f32.tf32.tf32.f32 "
        "{%0,%1,%2,%3}, {%4,%5,%6,%7}, {%8,%9}, {%0,%1,%2,%3};"
        : "+f"(d[0]), "+f"(d[1]), "+f"(d[2]), "+f"(d[3])
        : "r"(a[0]), "r"(a[1]), "r"(a[2]), "r"(a[3]), "r"(b[0]), "r"(b[1]));
}

template<int MODE>
__global__ __launch_bounds__(256) void gemm_tf32(
    const float* __restrict__ A, const float* __restrict__ W,
    const float* __restrict__ bias, const float* __restrict__ res,
    float* __restrict__ C, int N, int K)
{
    extern __shared__ float smem[];
    float* As = smem;                 // [2][BM][AS_STRIDE]
    float* Bs = smem + 2 * AS_BUF;    // [2][BK][BS_STRIDE]

    const int tid  = threadIdx.x;
    const int lane = tid & 31;
    const int warp = tid >> 5;
    const int wm = warp >> 2;          // 0..1
    const int wn = warp & 3;           // 0..3
    const int g  = lane >> 2;          // 0..7
    const int tg = lane & 3;           // 0..3

    const int bm = blockIdx.y * BM;
    const int bn = blockIdx.x * BN;

    // staging mappings
    const int am = tid >> 1;                 // A row 0..127
    const int ak = (tid & 1) * 16;           // A col base (4 float4)
    const int bk = tid >> 3;                 // B row 0..31
    const int bnc = (tid & 7) * 16;          // B col base (4 float4)

    const float* Ap = A + (size_t)(bm + am) * K + ak;
    const float* Wp = W + (size_t)bk * N + bn + bnc;

    float4 aS[4], bS[4];

    const int T = K / BK;

    // prologue: tile 0 -> regs -> smem buf 0
    #pragma unroll
    for (int i = 0; i < 4; i++) aS[i] = *(const float4*)(Ap + i * 4);
    #pragma unroll
    for (int i = 0; i < 4; i++) bS[i] = *(const float4*)(Wp + i * 4);
    {
        float* a0 = As + am * AS_STRIDE + ak;
        #pragma unroll
        for (int i = 0; i < 4; i++) {
            a0[i*4+0] = __uint_as_float(f2tf32(aS[i].x));
            a0[i*4+1] = __uint_as_float(f2tf32(aS[i].y));
            a0[i*4+2] = __uint_as_float(f2tf32(aS[i].z));
            a0[i*4+3] = __uint_as_float(f2tf32(aS[i].w));
        }
        float* b0 = Bs + bk * BS_STRIDE + bnc;
        #pragma unroll
        for (int i = 0; i < 4; i++) {
            b0[i*4+0] = __uint_as_float(f2tf32(bS[i].x));
            b0[i*4+1] = __uint_as_float(f2tf32(bS[i].y));
            b0[i*4+2] = __uint_as_float(f2tf32(bS[i].z));
            b0[i*4+3] = __uint_as_float(f2tf32(bS[i].w));
        }
    }
    __syncthreads();

    float acc[4][4][4] = {};
    const int m_base = wm * 64;
    const int n_base = wn * 32;

    for (int t = 0; t < T; t++) {
        // prefetch next tile to registers
        if (t + 1 < T) {
            const float* Apn = Ap + (t + 1) * BK;
            const float* Wpn = Wp + (size_t)(t + 1) * BK * N;
            #pragma unroll
            for (int i = 0; i < 4; i++) aS[i] = *(const float4*)(Apn + i * 4);
            #pragma unroll
            for (int i = 0; i < 4; i++) bS[i] = *(const float4*)(Wpn + i * 4);
        }

        const float* Ab = As + (t & 1) * AS_BUF;
        const float* Bb = Bs + (t & 1) * BS_BUF;

        #pragma unroll
        for (int ks = 0; ks < 4; ks++) {
            const int k0 = ks * 8;
            uint32_t af[4][4], bf[4][2];
            #pragma unroll
            for (int mt = 0; mt < 4; mt++) {
                const int r0 = m_base + mt * 16 + g;
                af[mt][0] = __float_as_uint(Ab[ r0      * AS_STRIDE + k0 + tg    ]);
                af[mt][1] = __float_as_uint(Ab[(r0 + 8) * AS_STRIDE + k0 + tg    ]);
                af[mt][2] = __float_as_uint(Ab[ r0      * AS_STRIDE + k0 + tg + 4]);
                af[mt][3] = __float_as_uint(Ab[(r0 + 8) * AS_STRIDE + k0 + tg + 4]);
            }
            #pragma unroll
            for (int nt = 0; nt < 4; nt++) {
                const int c0 = n_base + nt * 8 + g;
                bf[nt][0] = __float_as_uint(Bb[(k0 + tg    ) * BS_STRIDE + c0]);
                bf[nt][1] = __float_as_uint(Bb[(k0 + tg + 4) * BS_STRIDE + c0]);
            }
            #pragma unroll
            for (int mt = 0; mt < 4; mt++)
                #pragma unroll
                for (int nt = 0; nt < 4; nt++)
                    mma_tf32(acc[mt][nt], af[mt], bf[nt]);
        }

        // store next tile into other buffer
        if (t + 1 < T) {
            float* a0 = As + ((t + 1) & 1) * AS_BUF + am * AS_STRIDE + ak;
            #pragma unroll
            for (int i = 0; i < 4; i++) {
                a0[i*4+0] = __uint_as_float(f2tf32(aS[i].x));
                a0[i*4+1] = __uint_as_float(f2tf32(aS[i].y));
                a0[i*4+2] = __uint_as_float(f2tf32(aS[i].z));
                a0[i*4+3] = __uint_as_float(f2tf32(aS[i].w));
            }
            float* b0 = Bs + ((t + 1) & 1) * BS_BUF + bk * BS_STRIDE + bnc;
            #pragma unroll
            for (int i = 0; i < 4; i++) {
                b0[i*4+0] = __uint_as_float(f2tf32(bS[i].x));
                b0[i*4+1] = __uint_as_float(f2tf32(bS[i].y));
                b0[i*4+2] = __uint_as_float(f2tf32(bS[i].z));
                b0[i*4+3] = __uint_as_float(f2tf32(bS[i].w));
            }
            __syncthreads();
        }
    }

    // ---------------- epilogue ----------------
    #pragma unroll
    for (int mt = 0; mt < 4; mt++) {
        #pragma unroll
        for (int half = 0; half < 2; half++) {
            const int row = bm + m_base + mt * 16 + g + half * 8;
            #pragma unroll
            for (int nt = 0; nt < 4; nt++) {
                const int col = bn + n_base + nt * 8 + tg * 2;
                float v0 = acc[mt][nt][half * 2 + 0] + bias[col];
                float v1 = acc[mt][nt][half * 2 + 1] + bias[col + 1];
                if (MODE == 0) {
                    if (col     < 768) v0 = (v0 > 0.f) ? (v0 + 1.f) : __expf(v0);
                    if (col + 1 < 768) v1 = (v1 > 0.f) ? (v1 + 1.f) : __expf(v1);
                }
                if (MODE == 2) {
                    v0 = 0.5f * v0 * (1.f + tanhf(0.7978845608028654f * (v0 + 0.044715f * v0 * v0 * v0)));
                    v1 = 0.5f * v1 * (1.f + tanhf(0.7978845608028654f * (v1 + 0.044715f * v1 * v1 * v1)));
                }
                if (MODE == 1 || MODE == 3) {
                    const float2 r = *(const float2*)(res + (size_t)row * N + col);
                    v0 += r.x; v1 += r.y;
                }
                *(float2*)(C + (size_t)row * N + col) = make_float2(v0, v1);
            }
        }
    }
}

// ---------------- zero kv state ----------------
__global__ void zero_kv_kernel()
{
    const int i = blockIdx.x * blockDim.x + threadIdx.x;
    if (i < BH * HD * HD) g_kv[i] = 0.f;
    if (i < BH * HD)      g_ksum[i] = 0.f;
}

// ---------------- kv-state: kv[bh] += K^T V over a 512-row chunk ----------------
__global__ __launch_bounds__(256) void kv_kernel()
{
    const int bh = blockIdx.y;
    const int b  = bh / NH, h = bh % NH;
    const int nbase = blockIdx.x * 512;

    __shared__ float ks[64][64];
    __shared__ float vs[64][64];

    const int tid = threadIdx.x;
    const int tx = tid & 15, ty = tid >> 4;
    const int e0 = tx * 4, d0 = ty * 4;

    float acc[4][4] = {};
    float ksacc = 0.f;

    for (int rb = 0; rb < 512; rb += 64) {
        const float* base = g_qkv + (size_t)(b * SEQ + nbase + rb) * QKVN + h * HD;
        for (int i = tid; i < 1024; i += 256) {
            const int r = i >> 4, c = (i & 15) << 2;
            *(float4*)&ks[r][c] = *(const float4*)(base + (size_t)r * QKVN + 384 + c);
            *(float4*)&vs[r][c] = *(const float4*)(base + (size_t)r * QKVN + 768 + c);
        }
        __syncthreads();
        #pragma unroll 8
        for (int r = 0; r < 64; r++) {
            const float4 a  = *(const float4*)&ks[r][d0];
            const float4 bb = *(const float4*)&vs[r][e0];
            acc[0][0] += a.x * bb.x; acc[0][1] += a.x * bb.y; acc[0][2] += a.x * bb.z; acc[0][3] += a.x * bb.w;
            acc[1][0] += a.y * bb.x; acc[1][1] += a.y * bb.y; acc[1][2] += a.y * bb.z; acc[1][3] += a.y * bb.w;
            acc[2][0] += a.z * bb.x; acc[2][1] += a.z * bb.y; acc[2][2] += a.z * bb.z; acc[2][3] += a.z * bb.w;
            acc[3][0] += a.w * bb.x; acc[3][1] += a.w * bb.y; acc[3][2] += a.w * bb.z; acc[3][3] += a.w * bb.w;
        }
        if (tid < 64) {
            #pragma unroll
            for (int r = 0; r < 64; r++) ksacc += ks[r][tid];
        }
        __syncthreads();
    }

    float* kvp = g_kv + bh * (HD * HD);
    #pragma unroll
    for (int i = 0; i < 4; i++)
        #pragma unroll
        for (int j = 0; j < 4; j++)
            atomicAdd(&kvp[(d0 + i) * HD + (e0 + j)], acc[i][j]);
    if (tid < 64) atomicAdd(&g_ksum[bh * HD + tid], ksacc);
}

// ---------------- attn: o[n,e] = z[n] * sum_d q[n,d] * kv[d,e] ----------------
__global__ __launch_bounds__(256) void attn_kernel()
{
    const int bh = blockIdx.y;
    const int b  = bh / NH, h = bh % NH;
    const int nbase = blockIdx.x * 64;

    __shared__ float qs[64][64];
    __shared__ float kvs[64][64];
    __shared__ float kss[64];
    __shared__ float zs[64];

    const int tid = threadIdx.x;

    for (int i = tid; i < 1024; i += 256) {
        const int r = i >> 4, c = (i & 15) << 2;
        *(float4*)&kvs[r][c] = *(const float4*)(g_kv + bh * (HD * HD) + r * HD + c);
    }
    if (tid < 64) kss[tid] = g_ksum[bh * HD + tid];

    const float* qbase = g_qkv + (size_t)(b * SEQ + nbase) * QKVN + h * HD;
    for (int i = tid; i < 1024; i += 256) {
        const int r = i >> 4, c = (i & 15) << 2;
        *(float4*)&qs[r][c] = *(const float4*)(qbase + (size_t)r * QKVN + c);
    }
    __syncthreads();

    if (tid < 64) {
        float dot = 0.f;
        #pragma unroll
        for (int d = 0; d < 64; d++) dot += qs[tid][d] * kss[d];
        zs[tid] = 1.f / (dot + 1e-6f);
    }
    __syncthreads();

    const int tx = tid & 15, ty = tid >> 4;
    const int e0 = tx * 4, r0 = ty * 4;
    float acc[4][4] = {};
    #pragma unroll 8
    for (int d = 0; d < 64; d++) {
        const float4 bb = *(const float4*)&kvs[d][e0];
        const float a0 = qs[r0 + 0][d];
        const float a1 = qs[r0 + 1][d];
        const float a2 = qs[r0 + 2][d];
        const float a3 = qs[r0 + 3][d];
        acc[0][0] += a0 * bb.x; acc[0][1] += a0 * bb.y; acc[0][2] += a0 * bb.z; acc[0][3] += a0 * bb.w;
        acc[1][0] += a1 * bb.x; acc[1][1] += a1 * bb.y; acc[1][2] += a1 * bb.z; acc[1][3] += a1 * bb.w;
        acc[2][0] += a2 * bb.x; acc[2][1] += a2 * bb.y; acc[2][2] += a2 * bb.z; acc[2][3] += a2 * bb.w;
        acc[3][0] += a3 * bb.x; acc[3][1] += a3 * bb.y; acc[3][2] += a3 * bb.z; acc[3][3] += a3 * bb.w;
    }

    #pragma unroll
    for (int i = 0; i < 4; i++) {
        const float z = zs[r0 + i];
        float* op = g_attn + (size_t)(b * SEQ + nbase + r0 + i) * DIM + h * HD + e0;
        *(float4*)op = make_float4(acc[i][0] * z, acc[i][1] * z, acc[i][2] * z, acc[i][3] * z);
    }
}

// ---------------- launch ----------------
extern "C" void kernel_launch(void* const* d_in, const int* in_sizes, int n_in,
                              void* d_out, int out_size)
{
    const float* x      = (const float*)d_in[0];
    const float* n1g    = (const float*)d_in[1];
    const float* n1b    = (const float*)d_in[2];
    const float* qkv_w  = (const float*)d_in[3];
    const float* qkv_b  = (const float*)d_in[4];
    const float* proj_w = (const float*)d_in[5];
    const float* proj_b = (const float*)d_in[6];
    const float* n2g    = (const float*)d_in[7];
    const float* n2b    = (const float*)d_in[8];
    const float* fc1_w  = (const float*)d_in[9];
    const float* fc1_b  = (const float*)d_in[10];
    const float* fc2_w  = (const float*)d_in[11];
    const float* fc2_b  = (const float*)d_in[12];
    float* out = (float*)d_out;

    void *p_ln, *p_qkv, *p_attn, *p_x1, *p_mlp;
    cudaGetSymbolAddress(&p_ln,   g_ln);
    cudaGetSymbolAddress(&p_qkv,  g_qkv);
    cudaGetSymbolAddress(&p_attn, g_attn);
    cudaGetSymbolAddress(&p_x1,   g_x1);
    cudaGetSymbolAddress(&p_mlp,  g_mlp);
    float* ln   = (float*)p_ln;
    float* qkv  = (float*)p_qkv;
    float* attn = (float*)p_attn;
    float* x1   = (float*)p_x1;
    float* mlp  = (float*)p_mlp;

    cudaFuncSetAttribute(gemm_tf32<0>, cudaFuncAttributeMaxDynamicSharedMemorySize, GEMM_SMEM_BYTES);
    cudaFuncSetAttribute(gemm_tf32<1>, cudaFuncAttributeMaxDynamicSharedMemorySize, GEMM_SMEM_BYTES);
    cudaFuncSetAttribute(gemm_tf32<2>, cudaFuncAttributeMaxDynamicSharedMemorySize, GEMM_SMEM_BYTES);
    cudaFuncSetAttribute(gemm_tf32<3>, cudaFuncAttributeMaxDynamicSharedMemorySize, GEMM_SMEM_BYTES);

    // 1. LN1
    ln_kernel<<<M_TOK, 128>>>(x, n1g, n1b, ln);
    // 2. qkv GEMM + bias + phi on q,k
    gemm_tf32<0><<<dim3(QKVN / 128, M_TOK / 128), 256, GEMM_SMEM_BYTES>>>(ln, qkv_w, qkv_b, nullptr, qkv, QKVN, DIM);
    // 3. zero kv state, then accumulate kv = K^T V and ksum per (b,h)
    zero_kv_kernel<<<(BH * HD * HD + 255) / 256, 256>>>();
    kv_kernel<<<dim3(SEQ / 512, BH), 256>>>();
    // 4. attn = (q @ kv) * z
    attn_kernel<<<dim3(SEQ / 64, BH), 256>>>();
    // 5. proj GEMM + bias + residual(x) -> x1
    gemm_tf32<1><<<dim3(DIM / 128, M_TOK / 128), 256, GEMM_SMEM_BYTES>>>(attn, proj_w, proj_b, x, x1, DIM, DIM);
    // 6. LN2
    ln_kernel<<<M_TOK, 128>>>(x1, n2g, n2b, ln);
    // 7. fc1 GEMM + bias + gelu
    gemm_tf32<2><<<dim3(HID / 128, M_TOK / 128), 256, GEMM_SMEM_BYTES>>>(ln, fc1_w, fc1_b, nullptr, mlp, HID, DIM);
    // 8. fc2 GEMM + bias + residual(x1) -> out
    gemm_tf32<3><<<dim3(DIM / 128, M_TOK / 128), 256, GEMM_SMEM_BYTES>>>(mlp, fc2_w, fc2_b, x1, out, DIM, HID);
}

// round 3
// speedup vs baseline: 2.8736x; 1.6646x over previous
#include <cuda_runtime.h>
#include <math.h>
#include <stdint.h>

// ---------------- problem constants ----------------
#define M_TOK 32768          // 8 * 4096 tokens
#define SEQ   4096
#define DIM   384
#define NH    6
#define HD    64
#define BH    48             // batch*heads
#define QKVN  1152
#define HID   1536

// ---------------- scratch (static device arrays; no allocation) ----------------
__device__ float g_ln  [(size_t)M_TOK * DIM];
__device__ float g_qkv [(size_t)M_TOK * QKVN];
__device__ float g_attn[(size_t)M_TOK * DIM];
__device__ float g_x1  [(size_t)M_TOK * DIM];
__device__ float g_mlp [(size_t)M_TOK * HID];
__device__ float g_kv  [BH * HD * HD];
__device__ float g_ksum[BH * HD];

// ---------------- LayerNorm: one block per row of 384 ----------------
__global__ __launch_bounds__(128) void ln_kernel(
    const float* __restrict__ x, const float* __restrict__ gma,
    const float* __restrict__ bta, float* __restrict__ out)
{
    const int row = blockIdx.x;
    const float* xr = x + (size_t)row * DIM;
    float* orow = out + (size_t)row * DIM;
    const int tid = threadIdx.x;

    float v0 = xr[tid], v1 = xr[tid + 128], v2 = xr[tid + 256];
    float s  = v0 + v1 + v2;
    float sq = v0*v0 + v1*v1 + v2*v2;
    #pragma unroll
    for (int o = 16; o > 0; o >>= 1) {
        s  += __shfl_down_sync(0xffffffffu, s,  o);
        sq += __shfl_down_sync(0xffffffffu, sq, o);
    }
    __shared__ float ss[4], sqs[4];
    const int w = tid >> 5;
    if ((tid & 31) == 0) { ss[w] = s; sqs[w] = sq; }
    __syncthreads();
    if (tid == 0) {
        float S  = ss[0] + ss[1] + ss[2] + ss[3];
        float SQ = sqs[0] + sqs[1] + sqs[2] + sqs[3];
        float mean = S * (1.f / DIM);
        float var  = SQ * (1.f / DIM) - mean * mean;
        ss[0]  = mean;
        sqs[0] = rsqrtf(var + 1e-5f);
    }
    __syncthreads();
    const float mean = ss[0], inv = sqs[0];
    orow[tid      ] = (v0 - mean) * inv * gma[tid      ] + bta[tid      ];
    orow[tid + 128] = (v1 - mean) * inv * gma[tid + 128] + bta[tid + 128];
    orow[tid + 256] = (v2 - mean) * inv * gma[tid + 256] + bta[tid + 256];
}

// ---------------- tf32 tensor-core GEMM, cp.async 3-stage pipeline ----------------
// C[M,N] = A[M,K] @ W[K,N] + bias, fused epilogue per MODE:
//   MODE 0: qkv  -> phi(x)=elu(x)+1 on columns < 768
//   MODE 1: proj -> += residual
//   MODE 2: fc1  -> tanh gelu
//   MODE 3: fc2  -> += residual
// Tile: 128x128x32. 256 threads = 8 warps in 2x4; warp tile 64x32 = 4x4 m16n8k8.

#define BM 128
#define BN 128
#define BK 32
#define STAGES 3
#define AS_STRIDE 36
#define BS_STRIDE 136
#define AS_BUF (BM * AS_STRIDE)
#define BS_BUF (BK * BS_STRIDE)
#define GEMM_SMEM_BYTES (STAGES * (AS_BUF + BS_BUF) * 4)

__device__ __forceinline__ uint32_t f2tf32(float x) {
    uint32_t u;
    asm("cvt.rna.tf32.f32 %0, %1;" : "=r"(u) : "f"(x));
    return u;
}

__device__ __forceinline__ void cp16(float* dst, const float* src) {
    uint32_t s = (uint32_t)__cvta_generic_to_shared(dst);
    asm volatile("cp.async.cg.shared.global [%0], [%1], 16;" :: "r"(s), "l"(src));
}

__device__ __forceinline__ void mma_tf32(float* d, const uint32_t* a, const uint32_t* b) {
    asm volatile(
        "mma.sync.aligned.m16n8k8.row.col.f32.tf32.tf32.f32 "
        "{%0,%1,%2,%3}, {%4,%5,%6,%7}, {%8,%9}, {%0,%1,%2,%3};"
        : "+f"(d[0]), "+f"(d[1]), "+f"(d[2]), "+f"(d[3])
        : "r"(a[0]), "r"(a[1]), "r"(a[2]), "r"(a[3]), "r"(b[0]), "r"(b[1]));
}

template<int MODE>
__global__ __launch_bounds__(256, 2) void gemm_tf32(
    const float* __restrict__ A, const float* __restrict__ W,
    const float* __restrict__ bias, const float* __restrict__ res,
    float* __restrict__ C, int N, int K)
{
    extern __shared__ float smem[];
    float* As = smem;                          // [STAGES][BM][AS_STRIDE]
    float* Bs = smem + STAGES * AS_BUF;        // [STAGES][BK][BS_STRIDE]

    const int tid  = threadIdx.x;
    const int lane = tid & 31;
    const int warp = tid >> 5;
    const int wm = warp >> 2;          // 0..1
    const int wn = warp & 3;           // 0..3
    const int g  = lane >> 2;          // 0..7
    const int tg = lane & 3;           // 0..3

    const int bm = blockIdx.y * BM;
    const int bn = blockIdx.x * BN;

    // async-copy mappings
    const int ar = tid >> 3;            // A row group 0..31
    const int ac = (tid & 7) * 4;       // A col 0..28
    const int br = tid >> 5;            // B row group 0..7
    const int bc = (tid & 31) * 4;      // B col 0..124

    const int T = K / BK;

    // prologue: stages 0,1
    #pragma unroll
    for (int s = 0; s < 2; s++) {
        const int kt = s * BK;
        float* Ad = As + s * AS_BUF;
        float* Bd = Bs + s * BS_BUF;
        #pragma unroll
        for (int i = 0; i < 4; i++) {
            const int m = ar + i * 32;
            cp16(&Ad[m * AS_STRIDE + ac], A + (size_t)(bm + m) * K + kt + ac);
        }
        #pragma unroll
        for (int i = 0; i < 4; i++) {
            const int k = br + i * 8;
            cp16(&Bd[k * BS_STRIDE + bc], W + (size_t)(kt + k) * N + bn + bc);
        }
        asm volatile("cp.async.commit_group;");
    }

    float acc[4][4][4] = {};
    const int m_base = wm * 64;
    const int n_base = wn * 32;

    int buf = 0;
    for (int t = 0; t < T; t++) {
        asm volatile("cp.async.wait_group 1;");
        __syncthreads();

        const float* Ab = As + buf * AS_BUF;
        const float* Bb = Bs + buf * BS_BUF;

        #pragma unroll
        for (int ks = 0; ks < 4; ks++) {
            const int k0 = ks * 8;
            uint32_t af[4][4], bf[4][2];
            #pragma unroll
            for (int mt = 0; mt < 4; mt++) {
                const int r0 = m_base + mt * 16 + g;
                af[mt][0] = f2tf32(Ab[ r0      * AS_STRIDE + k0 + tg    ]);
                af[mt][1] = f2tf32(Ab[(r0 + 8) * AS_STRIDE + k0 + tg    ]);
                af[mt][2] = f2tf32(Ab[ r0      * AS_STRIDE + k0 + tg + 4]);
                af[mt][3] = f2tf32(Ab[(r0 + 8) * AS_STRIDE + k0 + tg + 4]);
            }
            #pragma unroll
            for (int nt = 0; nt < 4; nt++) {
                const int c0 = n_base + nt * 8 + g;
                bf[nt][0] = f2tf32(Bb[(k0 + tg    ) * BS_STRIDE + c0]);
                bf[nt][1] = f2tf32(Bb[(k0 + tg + 4) * BS_STRIDE + c0]);
            }
            #pragma unroll
            for (int mt = 0; mt < 4; mt++)
                #pragma unroll
                for (int nt = 0; nt < 4; nt++)
                    mma_tf32(acc[mt][nt], af[mt], bf[nt]);
        }

        // issue loads for stage t+2 (buffer being overwritten was consumed at t-1)
        if (t + 2 < T) {
            const int s  = (t + 2) % STAGES;
            const int kt = (t + 2) * BK;
            float* Ad = As + s * AS_BUF;
            float* Bd = Bs + s * BS_BUF;
            #pragma unroll
            for (int i = 0; i < 4; i++) {
                const int m = ar + i * 32;
                cp16(&Ad[m * AS_STRIDE + ac], A + (size_t)(bm + m) * K + kt + ac);
            }
            #pragma unroll
            for (int i = 0; i < 4; i++) {
                const int k = br + i * 8;
                cp16(&Bd[k * BS_STRIDE + bc], W + (size_t)(kt + k) * N + bn + bc);
            }
        }
        asm volatile("cp.async.commit_group;");

        buf = (buf + 1 == STAGES) ? 0 : buf + 1;
    }

    // ---------------- epilogue ----------------
    #pragma unroll
    for (int mt = 0; mt < 4; mt++) {
        #pragma unroll
        for (int half = 0; half < 2; half++) {
            const int row = bm + m_base + mt * 16 + g + half * 8;
            #pragma unroll
            for (int nt = 0; nt < 4; nt++) {
                const int col = bn + n_base + nt * 8 + tg * 2;
                float v0 = acc[mt][nt][half * 2 + 0] + bias[col];
                float v1 = acc[mt][nt][half * 2 + 1] + bias[col + 1];
                if (MODE == 0) {
                    if (col     < 768) v0 = (v0 > 0.f) ? (v0 + 1.f) : __expf(v0);
                    if (col + 1 < 768) v1 = (v1 > 0.f) ? (v1 + 1.f) : __expf(v1);
                }
                if (MODE == 2) {
                    v0 = 0.5f * v0 * (1.f + tanhf(0.7978845608028654f * (v0 + 0.044715f * v0 * v0 * v0)));
                    v1 = 0.5f * v1 * (1.f + tanhf(0.7978845608028654f * (v1 + 0.044715f * v1 * v1 * v1)));
                }
                if (MODE == 1 || MODE == 3) {
                    const float2 r = *(const float2*)(res + (size_t)row * N + col);
                    v0 += r.x; v1 += r.y;
                }
                *(float2*)(C + (size_t)row * N + col) = make_float2(v0, v1);
            }
        }
    }
}

// ---------------- zero kv state ----------------
__global__ void zero_kv_kernel()
{
    const int i = blockIdx.x * blockDim.x + threadIdx.x;
    if (i < BH * HD * HD) g_kv[i] = 0.f;
    if (i < BH * HD)      g_ksum[i] = 0.f;
}

// ---------------- kv-state: kv[bh] += K^T V over a 512-row chunk ----------------
__global__ __launch_bounds__(256) void kv_kernel()
{
    const int bh = blockIdx.y;
    const int b  = bh / NH, h = bh % NH;
    const int nbase = blockIdx.x * 512;

    __shared__ float ks[64][64];
    __shared__ float vs[64][64];

    const int tid = threadIdx.x;
    const int tx = tid & 15, ty = tid >> 4;
    const int e0 = tx * 4, d0 = ty * 4;

    float acc[4][4] = {};
    float ksacc = 0.f;

    for (int rb = 0; rb < 512; rb += 64) {
        const float* base = g_qkv + (size_t)(b * SEQ + nbase + rb) * QKVN + h * HD;
        for (int i = tid; i < 1024; i += 256) {
            const int r = i >> 4, c = (i & 15) << 2;
            *(float4*)&ks[r][c] = *(const float4*)(base + (size_t)r * QKVN + 384 + c);
            *(float4*)&vs[r][c] = *(const float4*)(base + (size_t)r * QKVN + 768 + c);
        }
        __syncthreads();
        #pragma unroll 8
        for (int r = 0; r < 64; r++) {
            const float4 a  = *(const float4*)&ks[r][d0];
            const float4 bb = *(const float4*)&vs[r][e0];
            acc[0][0] += a.x * bb.x; acc[0][1] += a.x * bb.y; acc[0][2] += a.x * bb.z; acc[0][3] += a.x * bb.w;
            acc[1][0] += a.y * bb.x; acc[1][1] += a.y * bb.y; acc[1][2] += a.y * bb.z; acc[1][3] += a.y * bb.w;
            acc[2][0] += a.z * bb.x; acc[2][1] += a.z * bb.y; acc[2][2] += a.z * bb.z; acc[2][3] += a.z * bb.w;
            acc[3][0] += a.w * bb.x; acc[3][1] += a.w * bb.y; acc[3][2] += a.w * bb.z; acc[3][3] += a.w * bb.w;
        }
        if (tid < 64) {
            #pragma unroll
            for (int r = 0; r < 64; r++) ksacc += ks[r][tid];
        }
        __syncthreads();
    }

    float* kvp = g_kv + bh * (HD * HD);
    #pragma unroll
    for (int i = 0; i < 4; i++)
        #pragma unroll
        for (int j = 0; j < 4; j++)
            atomicAdd(&kvp[(d0 + i) * HD + (e0 + j)], acc[i][j]);
    if (tid < 64) atomicAdd(&g_ksum[bh * HD + tid], ksacc);
}

// ---------------- attn: o[n,e] = z[n] * sum_d q[n,d] * kv[d,e] ----------------
__global__ __launch_bounds__(256) void attn_kernel()
{
    const int bh = blockIdx.y;
    const int b  = bh / NH, h = bh % NH;
    const int nbase = blockIdx.x * 64;

    __shared__ float qs[64][64];
    __shared__ float kvs[64][64];
    __shared__ float kss[64];
    __shared__ float zs[64];

    const int tid = threadIdx.x;

    for (int i = tid; i < 1024; i += 256) {
        const int r = i >> 4, c = (i & 15) << 2;
        *(float4*)&kvs[r][c] = *(const float4*)(g_kv + bh * (HD * HD) + r * HD + c);
    }
    if (tid < 64) kss[tid] = g_ksum[bh * HD + tid];

    const float* qbase = g_qkv + (size_t)(b * SEQ + nbase) * QKVN + h * HD;
    for (int i = tid; i < 1024; i += 256) {
        const int r = i >> 4, c = (i & 15) << 2;
        *(float4*)&qs[r][c] = *(const float4*)(qbase + (size_t)r * QKVN + c);
    }
    __syncthreads();

    if (tid < 64) {
        float dot = 0.f;
        #pragma unroll
        for (int d = 0; d < 64; d++) dot += qs[tid][d] * kss[d];
        zs[tid] = 1.f / (dot + 1e-6f);
    }
    __syncthreads();

    const int tx = tid & 15, ty = tid >> 4;
    const int e0 = tx * 4, r0 = ty * 4;
    float acc[4][4] = {};
    #pragma unroll 8
    for (int d = 0; d < 64; d++) {
        const float4 bb = *(const float4*)&kvs[d][e0];
        const float a0 = qs[r0 + 0][d];
        const float a1 = qs[r0 + 1][d];
        const float a2 = qs[r0 + 2][d];
        const float a3 = qs[r0 + 3][d];
        acc[0][0] += a0 * bb.x; acc[0][1] += a0 * bb.y; acc[0][2] += a0 * bb.z; acc[0][3] += a0 * bb.w;
        acc[1][0] += a1 * bb.x; acc[1][1] += a1 * bb.y; acc[1][2] += a1 * bb.z; acc[1][3] += a1 * bb.w;
        acc[2][0] += a2 * bb.x; acc[2][1] += a2 * bb.y; acc[2][2] += a2 * bb.z; acc[2][3] += a2 * bb.w;
        acc[3][0] += a3 * bb.x; acc[3][1] += a3 * bb.y; acc[3][2] += a3 * bb.z; acc[3][3] += a3 * bb.w;
    }

    #pragma unroll
    for (int i = 0; i < 4; i++) {
        const float z = zs[r0 + i];
        float* op = g_attn + (size_t)(b * SEQ + nbase + r0 + i) * DIM + h * HD + e0;
        *(float4*)op = make_float4(acc[i][0] * z, acc[i][1] * z, acc[i][2] * z, acc[i][3] * z);
    }
}

// ---------------- launch ----------------
extern "C" void kernel_launch(void* const* d_in, const int* in_sizes, int n_in,
                              void* d_out, int out_size)
{
    const float* x      = (const float*)d_in[0];
    const float* n1g    = (const float*)d_in[1];
    const float* n1b    = (const float*)d_in[2];
    const float* qkv_w  = (const float*)d_in[3];
    const float* qkv_b  = (const float*)d_in[4];
    const float* proj_w = (const float*)d_in[5];
    const float* proj_b = (const float*)d_in[6];
    const float* n2g    = (const float*)d_in[7];
    const float* n2b    = (const float*)d_in[8];
    const float* fc1_w  = (const float*)d_in[9];
    const float* fc1_b  = (const float*)d_in[10];
    const float* fc2_w  = (const float*)d_in[11];
    const float* fc2_b  = (const float*)d_in[12];
    float* out = (float*)d_out;

    void *p_ln, *p_qkv, *p_attn, *p_x1, *p_mlp;
    cudaGetSymbolAddress(&p_ln,   g_ln);
    cudaGetSymbolAddress(&p_qkv,  g_qkv);
    cudaGetSymbolAddress(&p_attn, g_attn);
    cudaGetSymbolAddress(&p_x1,   g_x1);
    cudaGetSymbolAddress(&p_mlp,  g_mlp);
    float* ln   = (float*)p_ln;
    float* qkv  = (float*)p_qkv;
    float* attn = (float*)p_attn;
    float* x1   = (float*)p_x1;
    float* mlp  = (float*)p_mlp;

    cudaFuncSetAttribute(gemm_tf32<0>, cudaFuncAttributeMaxDynamicSharedMemorySize, GEMM_SMEM_BYTES);
    cudaFuncSetAttribute(gemm_tf32<1>, cudaFuncAttributeMaxDynamicSharedMemorySize, GEMM_SMEM_BYTES);
    cudaFuncSetAttribute(gemm_tf32<2>, cudaFuncAttributeMaxDynamicSharedMemorySize, GEMM_SMEM_BYTES);
    cudaFuncSetAttribute(gemm_tf32<3>, cudaFuncAttributeMaxDynamicSharedMemorySize, GEMM_SMEM_BYTES);

    // 1. LN1
    ln_kernel<<<M_TOK, 128>>>(x, n1g, n1b, ln);
    // 2. qkv GEMM + bias + phi on q,k
    gemm_tf32<0><<<dim3(QKVN / 128, M_TOK / 128), 256, GEMM_SMEM_BYTES>>>(ln, qkv_w, qkv_b, nullptr, qkv, QKVN, DIM);
    // 3. zero kv state, then accumulate kv = K^T V and ksum per (b,h)
    zero_kv_kernel<<<(BH * HD * HD + 255) / 256, 256>>>();
    kv_kernel<<<dim3(SEQ / 512, BH), 256>>>();
    // 4. attn = (q @ kv) * z
    attn_kernel<<<dim3(SEQ / 64, BH), 256>>>();
    // 5. proj GEMM + bias + residual(x) -> x1
    gemm_tf32<1><<<dim3(DIM / 128, M_TOK / 128), 256, GEMM_SMEM_BYTES>>>(attn, proj_w, proj_b, x, x1, DIM, DIM);
    // 6. LN2
    ln_kernel<<<M_TOK, 128>>>(x1, n2g, n2b, ln);
    // 7. fc1 GEMM + bias + gelu
    gemm_tf32<2><<<dim3(HID / 128, M_TOK / 128), 256, GEMM_SMEM_BYTES>>>(ln, fc1_w, fc1_b, nullptr, mlp, HID, DIM);
    // 8. fc2 GEMM + bias + residual(x1) -> out
    gemm_tf32<3><<<dim3(DIM / 128, M_TOK / 128), 256, GEMM_SMEM_BYTES>>>(mlp, fc2_w, fc2_b, x1, out, DIM, HID);
}

// round 5
// speedup vs baseline: 3.3190x; 1.1550x over previous
#include <cuda_runtime.h>
#include <math.h>
#include <stdint.h>

// ---------------- problem constants ----------------
#define M_TOK 32768          // 8 * 4096 tokens
#define SEQ   4096
#define DIM   384
#define NH    6
#define HD    64
#define BH    48             // batch*heads
#define QKVN  1152
#define HID   1536

// ---------------- scratch (static device arrays; no allocation) ----------------
__device__ float g_ln  [(size_t)M_TOK * DIM];
__device__ float g_qkv [(size_t)M_TOK * QKVN];
__device__ float g_attn[(size_t)M_TOK * DIM];
__device__ float g_x1  [(size_t)M_TOK * DIM];
__device__ float g_mlp [(size_t)M_TOK * HID];
__device__ float g_kv  [BH * HD * HD];
__device__ float g_ksum[BH * HD];

// ---------------- LayerNorm: one block per row of 384 ----------------
__global__ __launch_bounds__(128) void ln_kernel(
    const float* __restrict__ x, const float* __restrict__ gma,
    const float* __restrict__ bta, float* __restrict__ out)
{
    const int row = blockIdx.x;
    const float* xr = x + (size_t)row * DIM;
    float* orow = out + (size_t)row * DIM;
    const int tid = threadIdx.x;

    float v0 = xr[tid], v1 = xr[tid + 128], v2 = xr[tid + 256];
    float s  = v0 + v1 + v2;
    float sq = v0*v0 + v1*v1 + v2*v2;
    #pragma unroll
    for (int o = 16; o > 0; o >>= 1) {
        s  += __shfl_down_sync(0xffffffffu, s,  o);
        sq += __shfl_down_sync(0xffffffffu, sq, o);
    }
    __shared__ float ss[4], sqs[4];
    const int w = tid >> 5;
    if ((tid & 31) == 0) { ss[w] = s; sqs[w] = sq; }
    __syncthreads();
    if (tid == 0) {
        float S  = ss[0] + ss[1] + ss[2] + ss[3];
        float SQ = sqs[0] + sqs[1] + sqs[2] + sqs[3];
        float mean = S * (1.f / DIM);
        float var  = SQ * (1.f / DIM) - mean * mean;
        ss[0]  = mean;
        sqs[0] = rsqrtf(var + 1e-5f);
    }
    __syncthreads();
    const float mean = ss[0], inv = sqs[0];
    orow[tid      ] = (v0 - mean) * inv * gma[tid      ] + bta[tid      ];
    orow[tid + 128] = (v1 - mean) * inv * gma[tid + 128] + bta[tid + 128];
    orow[tid + 256] = (v2 - mean) * inv * gma[tid + 256] + bta[tid + 256];
}

// ---------------- tf32 tensor-core GEMM, cp.async 3-stage pipeline ----------------
// C[M,N] = A[M,K] @ W[K,N] + bias, fused epilogue per MODE:
//   MODE 0: qkv  -> phi(x)=elu(x)+1 on columns < 768
//   MODE 1: proj -> += residual
//   MODE 2: fc1  -> fast gelu (sigmoid form)
//   MODE 3: fc2  -> += residual
// Tile: 128x128x32. 256 threads = 8 warps in 2x4; warp tile 64x32 = 4x4 m16n8k8.
// tf32 operands are RAW fp32 bits (HW truncates to 19 bits) — no cvt in mainloop.

#define BM 128
#define BN 128
#define BK 32
#define STAGES 3
#define AS_STRIDE 36
#define BS_STRIDE 136
#define AS_BUF (BM * AS_STRIDE)
#define BS_BUF (BK * BS_STRIDE)
#define GEMM_SMEM_BYTES (STAGES * (AS_BUF + BS_BUF) * 4)

__device__ __forceinline__ void cp16(float* dst, const float* src) {
    uint32_t s = (uint32_t)__cvta_generic_to_shared(dst);
    asm volatile("cp.async.cg.shared.global [%0], [%1], 16;" :: "r"(s), "l"(src));
}

__device__ __forceinline__ void mma_tf32(float* d, const uint32_t* a, const uint32_t* b) {
    asm volatile(
        "mma.sync.aligned.m16n8k8.row.col.f32.tf32.tf32.f32 "
        "{%0,%1,%2,%3}, {%4,%5,%6,%7}, {%8,%9}, {%0,%1,%2,%3};"
        : "+f"(d[0]), "+f"(d[1]), "+f"(d[2]), "+f"(d[3])
        : "r"(a[0]), "r"(a[1]), "r"(a[2]), "r"(a[3]), "r"(b[0]), "r"(b[1]));
}

__device__ __forceinline__ float fast_gelu(float v) {
    // 0.5*v*(1+tanh(u)) == v * sigmoid(2u),  u = 0.79788456*(v + 0.044715 v^3)
    const float two_u = 1.5957691216057308f * (v + 0.044715f * v * v * v);
    return v * (1.f / (1.f + __expf(-two_u)));
}

template<int MODE>
__global__ __launch_bounds__(256, 2) void gemm_tf32(
    const float* __restrict__ A, const float* __restrict__ W,
    const float* __restrict__ bias, const float* __restrict__ res,
    float* __restrict__ C, int N, int K)
{
    extern __shared__ float smem[];
    float* As = smem;                          // [STAGES][BM][AS_STRIDE]
    float* Bs = smem + STAGES * AS_BUF;        // [STAGES][BK][BS_STRIDE]

    const int tid  = threadIdx.x;
    const int lane = tid & 31;
    const int warp = tid >> 5;
    const int wm = warp >> 2;          // 0..1
    const int wn = warp & 3;           // 0..3
    const int g  = lane >> 2;          // 0..7
    const int tg = lane & 3;           // 0..3

    const int bm = blockIdx.y * BM;
    const int bn = blockIdx.x * BN;

    // async-copy mappings
    const int ar = tid >> 3;            // A row group 0..31
    const int ac = (tid & 7) * 4;       // A col 0..28
    const int br = tid >> 5;            // B row group 0..7
    const int bc = (tid & 31) * 4;      // B col 0..124

    const int T = K / BK;

    // prologue: stages 0,1
    #pragma unroll
    for (int s = 0; s < 2; s++) {
        const int kt = s * BK;
        float* Ad = As + s * AS_BUF;
        float* Bd = Bs + s * BS_BUF;
        #pragma unroll
        for (int i = 0; i < 4; i++) {
            const int m = ar + i * 32;
            cp16(&Ad[m * AS_STRIDE + ac], A + (size_t)(bm + m) * K + kt + ac);
        }
        #pragma unroll
        for (int i = 0; i < 4; i++) {
            const int k = br + i * 8;
            cp16(&Bd[k * BS_STRIDE + bc], W + (size_t)(kt + k) * N + bn + bc);
        }
        asm volatile("cp.async.commit_group;");
    }

    float acc[4][4][4] = {};
    const int m_base = wm * 64;
    const int n_base = wn * 32;

    int buf = 0;
    for (int t = 0; t < T; t++) {
        asm volatile("cp.async.wait_group 1;");
        __syncthreads();

        const float* Ab = As + buf * AS_BUF;
        const float* Bb = Bs + buf * BS_BUF;

        #pragma unroll
        for (int ks = 0; ks < 4; ks++) {
            const int k0 = ks * 8;
            uint32_t af[4][4], bf[4][2];
            #pragma unroll
            for (int mt = 0; mt < 4; mt++) {
                const int r0 = m_base + mt * 16 + g;
                af[mt][0] = __float_as_uint(Ab[ r0      * AS_STRIDE + k0 + tg    ]);
                af[mt][1] = __float_as_uint(Ab[(r0 + 8) * AS_STRIDE + k0 + tg    ]);
                af[mt][2] = __float_as_uint(Ab[ r0      * AS_STRIDE + k0 + tg + 4]);
                af[mt][3] = __float_as_uint(Ab[(r0 + 8) * AS_STRIDE + k0 + tg + 4]);
            }
            #pragma unroll
            for (int nt = 0; nt < 4; nt++) {
                const int c0 = n_base + nt * 8 + g;
                bf[nt][0] = __float_as_uint(Bb[(k0 + tg    ) * BS_STRIDE + c0]);
                bf[nt][1] = __float_as_uint(Bb[(k0 + tg + 4) * BS_STRIDE + c0]);
            }
            #pragma unroll
            for (int mt = 0; mt < 4; mt++)
                #pragma unroll
                for (int nt = 0; nt < 4; nt++)
                    mma_tf32(acc[mt][nt], af[mt], bf[nt]);
        }

        // issue loads for stage t+2
        if (t + 2 < T) {
            const int s  = (t + 2) % STAGES;
            const int kt = (t + 2) * BK;
            float* Ad = As + s * AS_BUF;
            float* Bd = Bs + s * BS_BUF;
            #pragma unroll
            for (int i = 0; i < 4; i++) {
                const int m = ar + i * 32;
                cp16(&Ad[m * AS_STRIDE + ac], A + (size_t)(bm + m) * K + kt + ac);
            }
            #pragma unroll
            for (int i = 0; i < 4; i++) {
                const int k = br + i * 8;
                cp16(&Bd[k * BS_STRIDE + bc], W + (size_t)(kt + k) * N + bn + bc);
            }
        }
        asm volatile("cp.async.commit_group;");

        buf = (buf + 1 == STAGES) ? 0 : buf + 1;
    }

    // ---------------- epilogue ----------------
    #pragma unroll
    for (int mt = 0; mt < 4; mt++) {
        #pragma unroll
        for (int half = 0; half < 2; half++) {
            const int row = bm + m_base + mt * 16 + g + half * 8;
            #pragma unroll
            for (int nt = 0; nt < 4; nt++) {
                const int col = bn + n_base + nt * 8 + tg * 2;
                float v0 = acc[mt][nt][half * 2 + 0] + bias[col];
                float v1 = acc[mt][nt][half * 2 + 1] + bias[col + 1];
                if (MODE == 0) {
                    if (col     < 768) v0 = (v0 > 0.f) ? (v0 + 1.f) : __expf(v0);
                    if (col + 1 < 768) v1 = (v1 > 0.f) ? (v1 + 1.f) : __expf(v1);
                }
                if (MODE == 2) {
                    v0 = fast_gelu(v0);
                    v1 = fast_gelu(v1);
                }
                if (MODE == 1 || MODE == 3) {
                    const float2 r = *(const float2*)(res + (size_t)row * N + col);
                    v0 += r.x; v1 += r.y;
                }
                *(float2*)(C + (size_t)row * N + col) = make_float2(v0, v1);
            }
        }
    }
}

// ---------------- zero kv state ----------------
__global__ void zero_kv_kernel()
{
    const int i = blockIdx.x * blockDim.x + threadIdx.x;
    if (i < BH * HD * HD) g_kv[i] = 0.f;
    if (i < BH * HD)      g_ksum[i] = 0.f;
}

// ---------------- kv-state: kv[bh] += K^T V over a 256-row chunk ----------------
#define KV_CHUNK 256
__global__ __launch_bounds__(256) void kv_kernel()
{
    const int bh = blockIdx.y;
    const int b  = bh / NH, h = bh % NH;
    const int nbase = blockIdx.x * KV_CHUNK;

    __shared__ float ks[64][64];
    __shared__ float vs[64][64];

    const int tid = threadIdx.x;
    const int tx = tid & 15, ty = tid >> 4;
    const int e0 = tx * 4, d0 = ty * 4;

    float acc[4][4] = {};
    float ksacc = 0.f;

    for (int rb = 0; rb < KV_CHUNK; rb += 64) {
        const float* base = g_qkv + (size_t)(b * SEQ + nbase + rb) * QKVN + h * HD;
        for (int i = tid; i < 1024; i += 256) {
            const int r = i >> 4, c = (i & 15) << 2;
            *(float4*)&ks[r][c] = *(const float4*)(base + (size_t)r * QKVN + 384 + c);
            *(float4*)&vs[r][c] = *(const float4*)(base + (size_t)r * QKVN + 768 + c);
        }
        __syncthreads();
        #pragma unroll 8
        for (int r = 0; r < 64; r++) {
            const float4 a  = *(const float4*)&ks[r][d0];
            const float4 bb = *(const float4*)&vs[r][e0];
            acc[0][0] += a.x * bb.x; acc[0][1] += a.x * bb.y; acc[0][2] += a.x * bb.z; acc[0][3] += a.x * bb.w;
            acc[1][0] += a.y * bb.x; acc[1][1] += a.y * bb.y; acc[1][2] += a.y * bb.z; acc[1][3] += a.y * bb.w;
            acc[2][0] += a.z * bb.x; acc[2][1] += a.z * bb.y; acc[2][2] += a.z * bb.z; acc[2][3] += a.z * bb.w;
            acc[3][0] += a.w * bb.x; acc[3][1] += a.w * bb.y; acc[3][2] += a.w * bb.z; acc[3][3] += a.w * bb.w;
        }
        if (tid < 64) {
            #pragma unroll
            for (int r = 0; r < 64; r++) ksacc += ks[r][tid];
        }
        __syncthreads();
    }

    float* kvp = g_kv + bh * (HD * HD);
    #pragma unroll
    for (int i = 0; i < 4; i++)
        #pragma unroll
        for (int j = 0; j < 4; j++)
            atomicAdd(&kvp[(d0 + i) * HD + (e0 + j)], acc[i][j]);
    if (tid < 64) atomicAdd(&g_ksum[bh * HD + tid], ksacc);
}

// ---------------- attn: o[n,e] = z[n] * sum_d q[n,d] * kv[d,e] ----------------
__global__ __launch_bounds__(256) void attn_kernel()
{
    const int bh = blockIdx.y;
    const int b  = bh / NH, h = bh % NH;
    const int nbase = blockIdx.x * 64;

    __shared__ float qs[64][64];
    __shared__ float kvs[64][64];
    __shared__ float kss[64];
    __shared__ float zs[64];

    const int tid = threadIdx.x;

    for (int i = tid; i < 1024; i += 256) {
        const int r = i >> 4, c = (i & 15) << 2;
        *(float4*)&kvs[r][c] = *(const float4*)(g_kv + bh * (HD * HD) + r * HD + c);
    }
    if (tid < 64) kss[tid] = g_ksum[bh * HD + tid];

    const float* qbase = g_qkv + (size_t)(b * SEQ + nbase) * QKVN + h * HD;
    for (int i = tid; i < 1024; i += 256) {
        const int r = i >> 4, c = (i & 15) << 2;
        *(float4*)&qs[r][c] = *(const float4*)(qbase + (size_t)r * QKVN + c);
    }
    __syncthreads();

    if (tid < 64) {
        float dot = 0.f;
        #pragma unroll
        for (int d = 0; d < 64; d++) dot += qs[tid][d] * kss[d];
        zs[tid] = 1.f / (dot + 1e-6f);
    }
    __syncthreads();

    const int tx = tid & 15, ty = tid >> 4;
    const int e0 = tx * 4, r0 = ty * 4;
    float acc[4][4] = {};
    #pragma unroll 8
    for (int d = 0; d < 64; d++) {
        const float4 bb = *(const float4*)&kvs[d][e0];
        const float a0 = qs[r0 + 0][d];
        const float a1 = qs[r0 + 1][d];
        const float a2 = qs[r0 + 2][d];
        const float a3 = qs[r0 + 3][d];
        acc[0][0] += a0 * bb.x; acc[0][1] += a0 * bb.y; acc[0][2] += a0 * bb.z; acc[0][3] += a0 * bb.w;
        acc[1][0] += a1 * bb.x; acc[1][1] += a1 * bb.y; acc[1][2] += a1 * bb.z; acc[1][3] += a1 * bb.w;
        acc[2][0] += a2 * bb.x; acc[2][1] += a2 * bb.y; acc[2][2] += a2 * bb.z; acc[2][3] += a2 * bb.w;
        acc[3][0] += a3 * bb.x; acc[3][1] += a3 * bb.y; acc[3][2] += a3 * bb.z; acc[3][3] += a3 * bb.w;
    }

    #pragma unroll
    for (int i = 0; i < 4; i++) {
        const float z = zs[r0 + i];
        float* op = g_attn + (size_t)(b * SEQ + nbase + r0 + i) * DIM + h * HD + e0;
        *(float4*)op = make_float4(acc[i][0] * z, acc[i][1] * z, acc[i][2] * z, acc[i][3] * z);
    }
}

// ---------------- launch ----------------
extern "C" void kernel_launch(void* const* d_in, const int* in_sizes, int n_in,
                              void* d_out, int out_size)
{
    const float* x      = (const float*)d_in[0];
    const float* n1g    = (const float*)d_in[1];
    const float* n1b    = (const float*)d_in[2];
    const float* qkv_w  = (const float*)d_in[3];
    const float* qkv_b  = (const float*)d_in[4];
    const float* proj_w = (const float*)d_in[5];
    const float* proj_b = (const float*)d_in[6];
    const float* n2g    = (const float*)d_in[7];
    const float* n2b    = (const float*)d_in[8];
    const float* fc1_w  = (const float*)d_in[9];
    const float* fc1_b  = (const float*)d_in[10];
    const float* fc2_w  = (const float*)d_in[11];
    const float* fc2_b  = (const float*)d_in[12];
    float* out = (float*)d_out;

    void *p_ln, *p_qkv, *p_attn, *p_x1, *p_mlp;
    cudaGetSymbolAddress(&p_ln,   g_ln);
    cudaGetSymbolAddress(&p_qkv,  g_qkv);
    cudaGetSymbolAddress(&p_attn, g_attn);
    cudaGetSymbolAddress(&p_x1,   g_x1);
    cudaGetSymbolAddress(&p_mlp,  g_mlp);
    float* ln   = (float*)p_ln;
    float* qkv  = (float*)p_qkv;
    float* attn = (float*)p_attn;
    float* x1   = (float*)p_x1;
    float* mlp  = (float*)p_mlp;

    cudaFuncSetAttribute(gemm_tf32<0>, cudaFuncAttributeMaxDynamicSharedMemorySize, GEMM_SMEM_BYTES);
    cudaFuncSetAttribute(gemm_tf32<1>, cudaFuncAttributeMaxDynamicSharedMemorySize, GEMM_SMEM_BYTES);
    cudaFuncSetAttribute(gemm_tf32<2>, cudaFuncAttributeMaxDynamicSharedMemorySize, GEMM_SMEM_BYTES);
    cudaFuncSetAttribute(gemm_tf32<3>, cudaFuncAttributeMaxDynamicSharedMemorySize, GEMM_SMEM_BYTES);

    // 1. LN1
    ln_kernel<<<M_TOK, 128>>>(x, n1g, n1b, ln);
    // 2. qkv GEMM + bias + phi on q,k
    gemm_tf32<0><<<dim3(QKVN / 128, M_TOK / 128), 256, GEMM_SMEM_BYTES>>>(ln, qkv_w, qkv_b, nullptr, qkv, QKVN, DIM);
    // 3. zero kv state, then accumulate kv = K^T V and ksum per (b,h)
    zero_kv_kernel<<<(BH * HD * HD + 255) / 256, 256>>>();
    kv_kernel<<<dim3(SEQ / KV_CHUNK, BH), 256>>>();
    // 4. attn = (q @ kv) * z
    attn_kernel<<<dim3(SEQ / 64, BH), 256>>>();
    // 5. proj GEMM + bias + residual(x) -> x1
    gemm_tf32<1><<<dim3(DIM / 128, M_TOK / 128), 256, GEMM_SMEM_BYTES>>>(attn, proj_w, proj_b, x, x1, DIM, DIM);
    // 6. LN2
    ln_kernel<<<M_TOK, 128>>>(x1, n2g, n2b, ln);
    // 7. fc1 GEMM + bias + gelu
    gemm_tf32<2><<<dim3(HID / 128, M_TOK / 128), 256, GEMM_SMEM_BYTES>>>(ln, fc1_w, fc1_b, nullptr, mlp, HID, DIM);
    // 8. fc2 GEMM + bias + residual(x1) -> out
    gemm_tf32<3><<<dim3(DIM / 128, M_TOK / 128), 256, GEMM_SMEM_BYTES>>>(mlp, fc2_w, fc2_b, x1, out, DIM, HID);
}